// round 5
// baseline (speedup 1.0000x reference)
#include <cuda_runtime.h>
#include <cuda_bf16.h>
#include <cstdint>
#include <math.h>

#define T_   1024
#define CV_  8
#define DIM_ 2048
#define NH_  32
#define BMM_ 2048   // NH*HD

// ---------------------------------------------------------------------------
// Scratch (device globals; no allocation allowed)
// ---------------------------------------------------------------------------
__device__ float g_q[T_ * BMM_];            // 8 MB
__device__ float g_k[T_ * CV_ * BMM_];      // 64 MB
__device__ float g_v[T_ * CV_ * BMM_];      // 64 MB
__device__ float g_att[T_ * BMM_];          // 8 MB

#define ROWS_X  T_
#define ROWS_C  (T_ * CV_)
#define ROWS_W  BMM_
__device__ __align__(16) char g_xq1[ROWS_X * DIM_],  g_xq2[ROWS_X * DIM_];
__device__ __align__(16) char g_cq1[ROWS_C * DIM_],  g_cq2[ROWS_C * DIM_];
__device__ __align__(16) char g_wqq1[ROWS_W * DIM_], g_wqq2[ROWS_W * DIM_];
__device__ __align__(16) char g_wkq1[ROWS_W * DIM_], g_wkq2[ROWS_W * DIM_];
__device__ __align__(16) char g_wvq1[ROWS_W * DIM_], g_wvq2[ROWS_W * DIM_];
__device__ __align__(16) char g_woq1[DIM_ * BMM_],   g_woq2[DIM_ * BMM_];
__device__ __align__(16) char g_aq1[T_ * BMM_],      g_aq2[T_ * BMM_];
__device__ float g_sx[ROWS_X], g_sc[ROWS_C], g_swq[ROWS_W], g_swk[ROWS_W],
                 g_swv[ROWS_W], g_swo[DIM_], g_sa[T_];

// ---------------------------------------------------------------------------
// helpers
// ---------------------------------------------------------------------------
__device__ __forceinline__ uint32_t smem_u32(const void* p) {
    uint32_t a;
    asm("{ .reg .u64 t; cvta.to.shared.u64 t, %1; cvt.u32.u64 %0, t; }"
        : "=r"(a) : "l"(p));
    return a;
}
// 64B-row swizzle: XOR 16B-chunk bits [4:5] with row bits [7:8]
__device__ __forceinline__ uint32_t swz64(uint32_t o) { return o ^ ((o >> 3) & 0x30); }

__device__ __forceinline__ void ldsm4(uint32_t& r0, uint32_t& r1, uint32_t& r2,
                                      uint32_t& r3, uint32_t a) {
    asm volatile("ldmatrix.sync.aligned.m8n8.x4.shared.b16 {%0,%1,%2,%3}, [%4];"
                 : "=r"(r0), "=r"(r1), "=r"(r2), "=r"(r3) : "r"(a));
}
__device__ __forceinline__ void imma(int* c, const uint32_t* a, const uint32_t* b) {
    asm volatile("mma.sync.aligned.m16n8k32.row.col.s32.s8.s8.s32 "
                 "{%0,%1,%2,%3}, {%4,%5,%6,%7}, {%8,%9}, {%0,%1,%2,%3};"
                 : "+r"(c[0]), "+r"(c[1]), "+r"(c[2]), "+r"(c[3])
                 : "r"(a[0]), "r"(a[1]), "r"(a[2]), "r"(a[3]), "r"(b[0]), "r"(b[1]));
}
__device__ __forceinline__ void cp16(uint32_t saddr, const void* gaddr) {
    asm volatile("cp.async.cg.shared.global [%0], [%1], 16;"
                 :: "r"(saddr), "l"(gaddr) : "memory");
}
__device__ __forceinline__ void cp_commit() {
    asm volatile("cp.async.commit_group;" ::: "memory");
}
template <int N> __device__ __forceinline__ void cp_wait() {
    asm volatile("cp.async.wait_group %0;" :: "n"(N) : "memory");
}

// ---------------------------------------------------------------------------
// Per-row 2-level int8 quantization: a = s*(a1 + a2/128), s = rowmax/127.
// One block per row (K = 2048, 256 threads, 8 elems/thread held in regs).
// ---------------------------------------------------------------------------
__global__ void __launch_bounds__(256)
quant_rows(const float* __restrict__ src, char* __restrict__ q1,
           char* __restrict__ q2, float* __restrict__ sc, int K) {
    const int row = blockIdx.x, tid = threadIdx.x;
    const float4* r4 = (const float4*)(src + (size_t)row * K);
    float4 f[2];
    f[0] = r4[tid];
    f[1] = r4[tid + 256];

    float m = 0.f;
#pragma unroll
    for (int j = 0; j < 2; j++) {
        m = fmaxf(m, fabsf(f[j].x)); m = fmaxf(m, fabsf(f[j].y));
        m = fmaxf(m, fabsf(f[j].z)); m = fmaxf(m, fabsf(f[j].w));
    }
#pragma unroll
    for (int o = 16; o; o >>= 1) m = fmaxf(m, __shfl_xor_sync(0xffffffffu, m, o));
    __shared__ float red[8];
    if ((tid & 31) == 0) red[tid >> 5] = m;
    __syncthreads();
    m = red[0];
#pragma unroll
    for (int i = 1; i < 8; i++) m = fmaxf(m, red[i]);

    const float inv = (m > 1e-30f) ? 127.f / m : 0.f;
    if (tid == 0) sc[row] = (m > 1e-30f) ? m / 127.f : 0.f;

#pragma unroll
    for (int j = 0; j < 2; j++) {
        const float qv[4] = {f[j].x * inv, f[j].y * inv, f[j].z * inv, f[j].w * inv};
        char4 c1, c2;
        float a1;
        a1 = rintf(qv[0]); c1.x = (char)(int)a1; c2.x = (char)__float2int_rn((qv[0] - a1) * 128.f);
        a1 = rintf(qv[1]); c1.y = (char)(int)a1; c2.y = (char)__float2int_rn((qv[1] - a1) * 128.f);
        a1 = rintf(qv[2]); c1.z = (char)(int)a1; c2.z = (char)__float2int_rn((qv[2] - a1) * 128.f);
        a1 = rintf(qv[3]); c1.w = (char)(int)a1; c2.w = (char)__float2int_rn((qv[3] - a1) * 128.f);
        const int idx = tid + j * 256;
        ((char4*)(q1 + (size_t)row * K))[idx] = c1;
        ((char4*)(q2 + (size_t)row * K))[idx] = c2;
    }
}

// ---------------------------------------------------------------------------
// INT8x3 GEMM: C[M,N] = diag(sA) * (A1 + A2/128)(B1 + B2/128)^T * diag(sB)
// dropping A2*B2. CTA tile 128x128, BK=64 (bytes), 8 warps (warp 64x32),
// 4-stage cp.async pipeline. int32 accumulation across all of K.
// ---------------------------------------------------------------------------
#define QBM 128
#define QBN 128
#define QBK 64
#define A1_OFF 0
#define A2_OFF 8192
#define B1_OFF 16384
#define B2_OFF 24576
#define QSTAGE 32768
#define QNST   4
#define QSMEM  (QNST * QSTAGE)   // 131072

__device__ __forceinline__ void q_load_stage(
    const char* __restrict__ A1, const char* __restrict__ A2,
    const char* __restrict__ B1, const char* __restrict__ B2,
    int bm, int bn, int K, int kc, uint32_t stg, int tid) {
#pragma unroll
    for (int j = 0; j < 2; j++) {
        const int idx = j * 256 + tid;
        const int r = idx >> 2, c = idx & 3;
        const uint32_t so = swz64((uint32_t)(r * 64 + c * 16));
        const size_t ga = (size_t)(bm + r) * K + kc + c * 16;
        const size_t gb = (size_t)(bn + r) * K + kc + c * 16;
        cp16(stg + A1_OFF + so, A1 + ga);
        cp16(stg + A2_OFF + so, A2 + ga);
        cp16(stg + B1_OFF + so, B1 + gb);
        cp16(stg + B2_OFF + so, B2 + gb);
    }
}

__global__ void __launch_bounds__(256, 1)
gemm_i8(const char* __restrict__ A1, const char* __restrict__ A2,
        const float* __restrict__ sA,
        const char* __restrict__ B1, const char* __restrict__ B2,
        const float* __restrict__ sB,
        float* __restrict__ C, int M, int N, int K) {
    extern __shared__ char sm[];
    const uint32_t sb = smem_u32(sm);
    const int tid  = threadIdx.x;
    const int lane = tid & 31;
    const int wid  = tid >> 5;
    const int wm   = wid >> 2;   // 0..1 (64-row slice)
    const int wn   = wid & 3;    // 0..3 (32-col slice)
    const int bm   = blockIdx.y * QBM;
    const int bn   = blockIdx.x * QBN;

    int hi[4][4][4], lo[4][4][4];
#pragma unroll
    for (int i = 0; i < 4; i++)
#pragma unroll
        for (int j = 0; j < 4; j++)
#pragma unroll
            for (int r = 0; r < 4; r++) { hi[i][j][r] = 0; lo[i][j][r] = 0; }

    const int NCHK = K / QBK;   // 32
    q_load_stage(A1, A2, B1, B2, bm, bn, K, 0,        sb,              tid); cp_commit();
    q_load_stage(A1, A2, B1, B2, bm, bn, K, QBK,      sb + QSTAGE,     tid); cp_commit();
    q_load_stage(A1, A2, B1, B2, bm, bn, K, 2 * QBK,  sb + 2 * QSTAGE, tid); cp_commit();

    const int lr   = (lane & 7) + ((lane >> 3) & 1) * 8;  // row within 16
    const int lc16 = lane >> 4;                           // 0/1 : 16B chunk

    for (int c = 0; c < NCHK; c++) {
        cp_wait<2>();
        __syncthreads();

        if (c + 3 < NCHK)
            q_load_stage(A1, A2, B1, B2, bm, bn, K, (c + 3) * QBK,
                         sb + (uint32_t)((c + 3) % QNST) * QSTAGE, tid);
        cp_commit();

        const uint32_t stg = sb + (uint32_t)(c % QNST) * QSTAGE;
#pragma unroll
        for (int ks = 0; ks < 2; ks++) {          // two k32 steps in BK=64
            uint32_t a1[4][4], a2[4][4];
#pragma unroll
            for (int mi = 0; mi < 4; mi++) {
                const int r = wm * 64 + mi * 16 + lr;
                const uint32_t so = swz64((uint32_t)(r * 64 + (ks * 2 + lc16) * 16));
                ldsm4(a1[mi][0], a1[mi][1], a1[mi][2], a1[mi][3], stg + A1_OFF + so);
                ldsm4(a2[mi][0], a2[mi][1], a2[mi][2], a2[mi][3], stg + A2_OFF + so);
            }
#pragma unroll
            for (int nj = 0; nj < 2; nj++) {      // two 16-row n-tiles (warp n=32)
                const int r = wn * 32 + nj * 16 + lr;
                const uint32_t so = swz64((uint32_t)(r * 64 + (ks * 2 + lc16) * 16));
                uint32_t h0, h1, h2, h3, l0, l1, l2, l3;
                ldsm4(h0, h1, h2, h3, stg + B1_OFF + so);
                ldsm4(l0, l1, l2, l3, stg + B2_OFF + so);
                uint32_t b0h[2] = {h0, h2}, b1h[2] = {h1, h3};
                uint32_t b0l[2] = {l0, l2}, b1l[2] = {l1, l3};
#pragma unroll
                for (int mi = 0; mi < 4; mi++) {
                    imma(hi[mi][nj * 2],     a1[mi], b0h);
                    imma(lo[mi][nj * 2],     a1[mi], b0l);
                    imma(lo[mi][nj * 2],     a2[mi], b0h);
                    imma(hi[mi][nj * 2 + 1], a1[mi], b1h);
                    imma(lo[mi][nj * 2 + 1], a1[mi], b1l);
                    imma(lo[mi][nj * 2 + 1], a2[mi], b1h);
                }
            }
        }
    }

    const int gr = lane >> 2, gc = (lane & 3) << 1;
#pragma unroll
    for (int mi = 0; mi < 4; mi++) {
        const int row0 = bm + wm * 64 + mi * 16 + gr;
        const float s0 = sA[row0], s1 = sA[row0 + 8];
#pragma unroll
        for (int nn = 0; nn < 4; nn++) {
            const int col = bn + wn * 32 + nn * 8 + gc;
            const float t0 = sB[col], t1 = sB[col + 1];
            const float v00 = s0 * t0 * ((float)hi[mi][nn][0] + (float)lo[mi][nn][0] * 0.0078125f);
            const float v01 = s0 * t1 * ((float)hi[mi][nn][1] + (float)lo[mi][nn][1] * 0.0078125f);
            const float v10 = s1 * t0 * ((float)hi[mi][nn][2] + (float)lo[mi][nn][2] * 0.0078125f);
            const float v11 = s1 * t1 * ((float)hi[mi][nn][3] + (float)lo[mi][nn][3] * 0.0078125f);
            *(float2*)(C + (size_t)row0 * N + col)       = make_float2(v00, v01);
            *(float2*)(C + (size_t)(row0 + 8) * N + col) = make_float2(v10, v11);
        }
    }
}

// ---------------------------------------------------------------------------
// Windowed attention. 64 keys/query: (w 0..7) x (cv 0..7), p = t+w-7;
// p<0 rows zero-padded (score 0 in softmax, zero v). RoPE drops out: q and k
// share the same per-t rotation -> dot products invariant; v unrotated.
// 256 threads = 4 (t,h) units of 64 threads.
// ---------------------------------------------------------------------------
__global__ void __launch_bounds__(256)
attn_kernel(const float* __restrict__ q, const float* __restrict__ k,
            const float* __restrict__ v, float* __restrict__ out) {
    const int t    = blockIdx.x;
    const int u    = threadIdx.x >> 6;
    const int ut   = threadIdx.x & 63;
    const int h    = blockIdx.y * 4 + u;
    const int lane = threadIdx.x & 31;
    const int wid  = threadIdx.x >> 5;

    __shared__ float4 qs4[4][16];
    __shared__ float  at[256];
    __shared__ float  wmax[8], wsum[8];

    if (ut < 16)
        qs4[u][ut] = ((const float4*)(q + (size_t)t * BMM_ + h * 64))[ut];
    __syncthreads();

    const int w = ut >> 3, cv = ut & 7, p = t + w - 7;
    float s = 0.f;
    if (p >= 0) {
        const float4* kr = (const float4*)(k + (size_t)(p * CV_ + cv) * BMM_ + h * 64);
#pragma unroll
        for (int i = 0; i < 16; i++) {
            float4 a = qs4[u][i], b = kr[i];
            s = fmaf(a.x, b.x, s); s = fmaf(a.y, b.y, s);
            s = fmaf(a.z, b.z, s); s = fmaf(a.w, b.w, s);
        }
        s *= 0.125f;   // 1/sqrt(64)
    }

    float m = s;
#pragma unroll
    for (int o = 16; o; o >>= 1) m = fmaxf(m, __shfl_xor_sync(0xffffffffu, m, o));
    if (lane == 0) wmax[wid] = m;
    __syncthreads();
    const float mx = fmaxf(wmax[u * 2], wmax[u * 2 + 1]);

    const float e = expf(s - mx);
    float sum = e;
#pragma unroll
    for (int o = 16; o; o >>= 1) sum += __shfl_xor_sync(0xffffffffu, sum, o);
    if (lane == 0) wsum[wid] = sum;
    __syncthreads();
    at[threadIdx.x] = e / (wsum[u * 2] + wsum[u * 2 + 1]);
    __syncthreads();

    float acc = 0.f;
#pragma unroll
    for (int j = 0; j < 64; j++) {
        const int pj = t + (j >> 3) - 7;
        if (pj >= 0)
            acc = fmaf(at[u * 64 + j],
                       v[(size_t)(pj * CV_ + (j & 7)) * BMM_ + h * 64 + ut],
                       acc);
    }
    out[(size_t)t * BMM_ + h * 64 + ut] = acc;
}

// ---------------------------------------------------------------------------
extern "C" void kernel_launch(void* const* d_in, const int* in_sizes, int n_in,
                              void* d_out, int out_size) {
    const float* x     = (const float*)d_in[0];
    const float* chars = (const float*)d_in[1];
    const float* wq    = (const float*)d_in[2];
    const float* wk    = (const float*)d_in[3];
    const float* wv    = (const float*)d_in[4];
    const float* wo    = (const float*)d_in[5];
    float* out = (float*)d_out;

    float *q, *k, *v, *att;
    char *xq1, *xq2, *cq1, *cq2, *wqq1, *wqq2, *wkq1, *wkq2, *wvq1, *wvq2,
         *woq1, *woq2, *aq1, *aq2;
    float *sx, *sc, *swq, *swk, *swv, *swo, *sa;
    cudaGetSymbolAddress((void**)&q,    g_q);
    cudaGetSymbolAddress((void**)&k,    g_k);
    cudaGetSymbolAddress((void**)&v,    g_v);
    cudaGetSymbolAddress((void**)&att,  g_att);
    cudaGetSymbolAddress((void**)&xq1,  g_xq1);  cudaGetSymbolAddress((void**)&xq2,  g_xq2);
    cudaGetSymbolAddress((void**)&cq1,  g_cq1);  cudaGetSymbolAddress((void**)&cq2,  g_cq2);
    cudaGetSymbolAddress((void**)&wqq1, g_wqq1); cudaGetSymbolAddress((void**)&wqq2, g_wqq2);
    cudaGetSymbolAddress((void**)&wkq1, g_wkq1); cudaGetSymbolAddress((void**)&wkq2, g_wkq2);
    cudaGetSymbolAddress((void**)&wvq1, g_wvq1); cudaGetSymbolAddress((void**)&wvq2, g_wvq2);
    cudaGetSymbolAddress((void**)&woq1, g_woq1); cudaGetSymbolAddress((void**)&woq2, g_woq2);
    cudaGetSymbolAddress((void**)&aq1,  g_aq1);  cudaGetSymbolAddress((void**)&aq2,  g_aq2);
    cudaGetSymbolAddress((void**)&sx,  g_sx);  cudaGetSymbolAddress((void**)&sc,  g_sc);
    cudaGetSymbolAddress((void**)&swq, g_swq); cudaGetSymbolAddress((void**)&swk, g_swk);
    cudaGetSymbolAddress((void**)&swv, g_swv); cudaGetSymbolAddress((void**)&swo, g_swo);
    cudaGetSymbolAddress((void**)&sa,  g_sa);

    cudaFuncSetAttribute(gemm_i8, cudaFuncAttributeMaxDynamicSharedMemorySize, QSMEM);

    quant_rows<<<ROWS_X, 256>>>(x,     xq1,  xq2,  sx,  DIM_);
    quant_rows<<<ROWS_C, 256>>>(chars, cq1,  cq2,  sc,  DIM_);
    quant_rows<<<ROWS_W, 256>>>(wq,    wqq1, wqq2, swq, DIM_);
    quant_rows<<<ROWS_W, 256>>>(wk,    wkq1, wkq2, swk, DIM_);
    quant_rows<<<ROWS_W, 256>>>(wv,    wvq1, wvq2, swv, DIM_);
    quant_rows<<<DIM_,   256>>>(wo,    woq1, woq2, swo, BMM_);

    gemm_i8<<<dim3(BMM_ / QBN, T_ / QBM), 256, QSMEM>>>(
        xq1, xq2, sx, wqq1, wqq2, swq, q, T_, BMM_, DIM_);
    gemm_i8<<<dim3(BMM_ / QBN, (T_ * CV_) / QBM), 256, QSMEM>>>(
        cq1, cq2, sc, wkq1, wkq2, swk, k, T_ * CV_, BMM_, DIM_);
    gemm_i8<<<dim3(BMM_ / QBN, (T_ * CV_) / QBM), 256, QSMEM>>>(
        cq1, cq2, sc, wvq1, wvq2, swv, v, T_ * CV_, BMM_, DIM_);

    attn_kernel<<<dim3(T_, NH_ / 4), 256>>>(q, k, v, att);

    quant_rows<<<T_, 256>>>(att, aq1, aq2, sa, BMM_);
    gemm_i8<<<dim3(DIM_ / QBN, T_ / QBM), 256, QSMEM>>>(
        aq1, aq2, sa, woq1, woq2, swo, out, T_, DIM_, BMM_);
}